// round 1
// baseline (speedup 1.0000x reference)
#include <cuda_runtime.h>
#include <math.h>

// Problem constants
#define Bq 4
#define Hh 16
#define Ss 4096
#define Dd 128
#define Mm 128
#define BH (Bq*Hh)
#define EPSV 1e-6f

// Scratch (no cudaMalloc allowed)
__device__ float g_S[BH*Dd*Mm];   // S_t accumulator  [BH, D, M]  (4 MB)
__device__ float g_w[BH*Dd];      // w[d] = S*z_prev[d] + sum_s phi(k)[s,d]

__device__ __forceinline__ float phi(float x) {
    // elu(x)+1 = x+1 (x>0) else exp(x)
    return x > 0.f ? x + 1.f : expf(x);
}

// ---------------------------------------------------------------------------
// Kernel 0: init scratch: g_S = S_prev, g_w = S * z_prev
// ---------------------------------------------------------------------------
__global__ void k_init(const float* __restrict__ S_prev,
                       const float* __restrict__ z_prev) {
    int head = blockIdx.x;
    const float* sp = S_prev + (size_t)head * Dd * Mm;
    float* sg = g_S + (size_t)head * Dd * Mm;
    for (int i = threadIdx.x; i < Dd * Mm; i += blockDim.x)
        sg[i] = sp[i];
    for (int i = threadIdx.x; i < Dd; i += blockDim.x)
        g_w[head * Dd + i] = (float)Ss * z_prev[head * Dd + i];
}

// ---------------------------------------------------------------------------
// Kernel 1: split-S reduction  S_t += phi(k)^T * v   and  ksum += sum_s phi(k)
// grid: (S_CHUNKS, BH), 256 threads, each thread owns 8x8 of the 128x128 tile
// ---------------------------------------------------------------------------
#define P1_CHUNK 512
#define P1_TS 16

__global__ void __launch_bounds__(256, 2)
k_phase1(const float* __restrict__ kk, const float* __restrict__ vv,
         const float* __restrict__ mask) {
    int head = blockIdx.y;
    int s_base = blockIdx.x * P1_CHUNK;

    __shared__ float ks[P1_TS][Dd + 1];
    __shared__ float vs[P1_TS][Mm + 1];

    int tid = threadIdx.x;
    int tx = tid & 15;          // m-block 0..15
    int ty = tid >> 4;          // d-block 0..15
    int d0 = ty * 8, m0 = tx * 8;

    float C[8][8];
#pragma unroll
    for (int i = 0; i < 8; i++)
#pragma unroll
        for (int j = 0; j < 8; j++) C[i][j] = 0.f;
    float ksum[8];
#pragma unroll
    for (int i = 0; i < 8; i++) ksum[i] = 0.f;

    const float* kh = kk + (size_t)head * Ss * Dd;
    const float* vh = vv + (size_t)head * Ss * Mm;
    const float* mh = mask + (size_t)head * Ss;

    for (int s0 = s_base; s0 < s_base + P1_CHUNK; s0 += P1_TS) {
        __syncthreads();
        // load 16 x 128 of k (phi + mask) and v (mask); 2048 elems each / 256 thr
        for (int i = tid; i < P1_TS * Dd; i += 256) {
            int r = i >> 7;
            int c = i & 127;
            float mval = mh[s0 + r];
            ks[r][c] = phi(kh[(size_t)(s0 + r) * Dd + c]) * mval;
            vs[r][c] = vh[(size_t)(s0 + r) * Mm + c] * mval;
        }
        __syncthreads();
#pragma unroll
        for (int t = 0; t < P1_TS; t++) {
            float a[8], b[8];
#pragma unroll
            for (int i = 0; i < 8; i++) a[i] = ks[t][d0 + i];
#pragma unroll
            for (int j = 0; j < 8; j++) b[j] = vs[t][m0 + j];
#pragma unroll
            for (int i = 0; i < 8; i++) {
                ksum[i] += a[i];
#pragma unroll
                for (int j = 0; j < 8; j++) C[i][j] += a[i] * b[j];
            }
        }
    }

    float* Sg = g_S + (size_t)head * Dd * Mm;
#pragma unroll
    for (int i = 0; i < 8; i++)
#pragma unroll
        for (int j = 0; j < 8; j++)
            atomicAdd(&Sg[(size_t)(d0 + i) * Mm + m0 + j], C[i][j]);
    if (tx == 0) {
#pragma unroll
        for (int i = 0; i < 8; i++)
            atomicAdd(&g_w[head * Dd + d0 + i], ksum[i]);
    }
}

// ---------------------------------------------------------------------------
// Kernel 2: out[s,m] = (phi(q) @ S_t)[s,m] / (phi(q) . w + eps)
// grid: (S/128, BH), 256 threads, 8x8 per thread, S_t cached in smem
// ---------------------------------------------------------------------------
#define SM2_BYTES ((Dd*(Mm+1) + Dd + 128*17) * 4)

__global__ void __launch_bounds__(256, 2)
k_phase2(const float* __restrict__ qq, float* __restrict__ out) {
    int head = blockIdx.y;
    int s_base = blockIdx.x * 128;

    extern __shared__ float sm[];
    float (*Ssm)[Mm + 1] = (float (*)[Mm + 1])sm;        // 128 x 129
    float* ws = sm + Dd * (Mm + 1);                      // 128
    float (*qs)[17] = (float (*)[17])(ws + Dd);          // 128 x 17

    int tid = threadIdx.x;
    int tx = tid & 15;
    int ty = tid >> 4;
    int srow0 = ty * 8, m0 = tx * 8;

    const float* Sg = g_S + (size_t)head * Dd * Mm;
    for (int i = tid; i < Dd * Mm; i += 256) Ssm[i >> 7][i & 127] = Sg[i];
    for (int i = tid; i < Dd; i += 256) ws[i] = g_w[head * Dd + i];

    float C[8][8];
#pragma unroll
    for (int i = 0; i < 8; i++)
#pragma unroll
        for (int j = 0; j < 8; j++) C[i][j] = 0.f;
    float den[8];
#pragma unroll
    for (int i = 0; i < 8; i++) den[i] = 0.f;

    const float* qh = qq + (size_t)head * Ss * Dd;

    for (int kc = 0; kc < Dd; kc += 16) {
        __syncthreads();
        // load phi(q) tile: 128 rows x 16 d
        for (int i = tid; i < 128 * 16; i += 256) {
            int r = i >> 4;
            int c = i & 15;
            qs[r][c] = phi(qh[(size_t)(s_base + r) * Dd + kc + c]);
        }
        __syncthreads();
#pragma unroll
        for (int t = 0; t < 16; t++) {
            float a[8], b[8];
            float wv = ws[kc + t];
#pragma unroll
            for (int i = 0; i < 8; i++) a[i] = qs[srow0 + i][t];
#pragma unroll
            for (int j = 0; j < 8; j++) b[j] = Ssm[kc + t][m0 + j];
#pragma unroll
            for (int i = 0; i < 8; i++) {
                den[i] += a[i] * wv;
#pragma unroll
                for (int j = 0; j < 8; j++) C[i][j] += a[i] * b[j];
            }
        }
    }

    float* oh = out + (size_t)head * Ss * Mm;
#pragma unroll
    for (int i = 0; i < 8; i++) {
        float inv = 1.f / (den[i] + EPSV);
        size_t row = (size_t)(s_base + srow0 + i) * Mm + m0;
#pragma unroll
        for (int j = 0; j < 8; j++) oh[row + j] = C[i][j] * inv;
    }
}

// ---------------------------------------------------------------------------
// Kernel 3 (optional): copy S_t scratch into output region
// ---------------------------------------------------------------------------
__global__ void k_copyS(float* __restrict__ dst) {
    size_t i = (size_t)blockIdx.x * blockDim.x + threadIdx.x;
    if (i < (size_t)BH * Dd * Mm) dst[i] = g_S[i];
}

// ---------------------------------------------------------------------------
// Kernel 4 (optional): z_t[head,d,s] = z_prev[head,d] + phi(k)[head,s,d]*mask
// tiled transpose, 32x32 tiles
// ---------------------------------------------------------------------------
__global__ void k_zt(const float* __restrict__ kk, const float* __restrict__ mask,
                     const float* __restrict__ z_prev, float* __restrict__ zt) {
    __shared__ float tile[32][33];
    int head = blockIdx.z;
    int s0 = blockIdx.x * 32;
    int d0 = blockIdx.y * 32;
    int tx = threadIdx.x, ty = threadIdx.y;   // 32 x 8
    const float* kh = kk + (size_t)head * Ss * Dd;
    const float* mh = mask + (size_t)head * Ss;
    for (int r = ty; r < 32; r += 8) {
        int s = s0 + r;
        tile[r][tx] = phi(kh[(size_t)s * Dd + d0 + tx]) * mh[s];
    }
    __syncthreads();
    float* zth = zt + (size_t)head * Dd * Ss;
    for (int r = ty; r < 32; r += 8) {
        int d = d0 + r;
        zth[(size_t)d * Ss + s0 + tx] = tile[tx][r] + z_prev[head * Dd + d];
    }
}

// ---------------------------------------------------------------------------
extern "C" void kernel_launch(void* const* d_in, const int* in_sizes, int n_in,
                              void* d_out, int out_size) {
    (void)in_sizes; (void)n_in;
    const float* q      = (const float*)d_in[0];
    const float* k      = (const float*)d_in[1];
    const float* v      = (const float*)d_in[2];
    const float* mask   = (const float*)d_in[3];
    const float* S_prev = (const float*)d_in[4];
    const float* z_prev = (const float*)d_in[5];
    float* out = (float*)d_out;

    cudaFuncSetAttribute(k_phase2, cudaFuncAttributeMaxDynamicSharedMemorySize,
                         SM2_BYTES);

    k_init<<<BH, 256>>>(S_prev, z_prev);

    dim3 g1(Ss / P1_CHUNK, BH);
    k_phase1<<<g1, 256>>>(k, v, mask);

    dim3 g2(Ss / 128, BH);
    k_phase2<<<g2, 256, SM2_BYTES>>>(q, out);

    // Adapt to output layout: tuple (out, S_t, z_t) may be concatenated.
    const long N_OUT = (long)BH * Ss * Mm;       // 33,554,432
    const long N_ST  = (long)BH * Dd * Mm;       //  1,048,576
    const long N_ZT  = (long)BH * Dd * Ss;       // 33,554,432
    long osz = (long)out_size;
    if (osz >= N_OUT + N_ST) {
        k_copyS<<<(int)((N_ST + 255) / 256), 256>>>(out + N_OUT);
    }
    if (osz >= N_OUT + N_ST + N_ZT) {
        dim3 gz(Ss / 32, Dd / 32, BH);
        k_zt<<<gz, dim3(32, 8)>>>(k, mask, z_prev, out + N_OUT + N_ST);
    }
}

// round 2
// speedup vs baseline: 1.0490x; 1.0490x over previous
#include <cuda_runtime.h>
#include <math.h>

#define Bq 4
#define Hh 16
#define Ss 4096
#define Dd 128
#define Mm 128
#define BH (Bq*Hh)
#define EPSV 1e-6f

// Scratch (no cudaMalloc allowed)
__device__ float g_S[BH*Dd*Mm];   // S_t accumulator [BH, D, M]
__device__ float g_w[BH*Dd];      // w[d] = S*z_prev[d] + sum_s phi(k)[s,d]

__device__ __forceinline__ float phi(float x) {
    return x > 0.f ? x + 1.f : expf(x);
}
__device__ __forceinline__ unsigned f2tf(float x) {
    unsigned r; asm("cvt.rna.tf32.f32 %0, %1;" : "=r"(r) : "f"(x)); return r;
}
__device__ __forceinline__ void mma8(float* c, const unsigned* a, const unsigned* b) {
    asm volatile(
        "mma.sync.aligned.m16n8k8.row.col.f32.tf32.tf32.f32 "
        "{%0,%1,%2,%3}, {%4,%5,%6,%7}, {%8,%9}, {%0,%1,%2,%3};"
        : "+f"(c[0]), "+f"(c[1]), "+f"(c[2]), "+f"(c[3])
        : "r"(a[0]), "r"(a[1]), "r"(a[2]), "r"(a[3]), "r"(b[0]), "r"(b[1]));
}

// ---------------------------------------------------------------------------
// Kernel 0: init scratch: g_S = S_prev, g_w = S * z_prev
// ---------------------------------------------------------------------------
__global__ void k_init(const float* __restrict__ S_prev,
                       const float* __restrict__ z_prev) {
    int head = blockIdx.x;
    const float* sp = S_prev + (size_t)head * Dd * Mm;
    float* sg = g_S + (size_t)head * Dd * Mm;
    for (int i = threadIdx.x; i < Dd * Mm; i += blockDim.x)
        sg[i] = sp[i];
    for (int i = threadIdx.x; i < Dd; i += blockDim.x)
        g_w[head * Dd + i] = (float)Ss * z_prev[head * Dd + i];
}

// ---------------------------------------------------------------------------
// Kernel 1 (tensor): S_t += phi(k)^T * v  and  ksum += sum_s phi(k)
// grid (4, BH), 256 thr (8 warps). warp w owns d-rows [16w,16w+16), all 128 m.
// mma m16n8k8 tf32: A[d,s] (transposed read of smem ks[s][d]), B[s,m].
// ---------------------------------------------------------------------------
#define P1_CHUNK 1024
#define P1_ST 32
#define PITCH1 136   // pitch % 32 == 8 -> conflict-free fragment LDS

__global__ void __launch_bounds__(256)
k_phase1(const float* __restrict__ kk, const float* __restrict__ vv,
         const float* __restrict__ mask) {
    int head = blockIdx.y;
    int sbase = blockIdx.x * P1_CHUNK;

    __shared__ unsigned ks[P1_ST][PITCH1];
    __shared__ unsigned vs[P1_ST][PITCH1];
    __shared__ float ksum[Dd];

    int tid = threadIdx.x;
    int warp = tid >> 5, lane = tid & 31;
    int gid = lane >> 2, tig = lane & 3;
    int dw = warp * 16;

    if (tid < Dd) ksum[tid] = 0.f;

    float acc[16][4];
#pragma unroll
    for (int j = 0; j < 16; j++)
#pragma unroll
        for (int t = 0; t < 4; t++) acc[j][t] = 0.f;

    const float* kh = kk + (size_t)head * Ss * Dd;
    const float* vh = vv + (size_t)head * Ss * Mm;
    const float* mh = mask + (size_t)head * Ss;

    for (int s0 = sbase; s0 < sbase + P1_CHUNK; s0 += P1_ST) {
        __syncthreads();
        for (int i = tid; i < P1_ST * Dd; i += 256) {
            int r = i >> 7, c = i & 127;
            float mval = mh[s0 + r];
            float kv = phi(kh[(size_t)(s0 + r) * Dd + c]) * mval;
            ks[r][c] = f2tf(kv);
            atomicAdd(&ksum[c], kv);
            vs[r][c] = f2tf(vh[(size_t)(s0 + r) * Mm + c] * mval);
        }
        __syncthreads();
#pragma unroll
        for (int k8 = 0; k8 < P1_ST; k8 += 8) {
            unsigned a[4];
            a[0] = ks[k8 + tig][dw + gid];
            a[1] = ks[k8 + tig][dw + gid + 8];
            a[2] = ks[k8 + tig + 4][dw + gid];
            a[3] = ks[k8 + tig + 4][dw + gid + 8];
#pragma unroll
            for (int j = 0; j < 16; j++) {
                unsigned b[2] = { vs[k8 + tig][j * 8 + gid],
                                  vs[k8 + tig + 4][j * 8 + gid] };
                mma8(acc[j], a, b);
            }
        }
    }
    __syncthreads();

    float* Sg = g_S + (size_t)head * Dd * Mm;
#pragma unroll
    for (int j = 0; j < 16; j++) {
        int m0 = j * 8 + tig * 2;
        atomicAdd(&Sg[(size_t)(dw + gid) * Mm + m0],     acc[j][0]);
        atomicAdd(&Sg[(size_t)(dw + gid) * Mm + m0 + 1], acc[j][1]);
        atomicAdd(&Sg[(size_t)(dw + gid + 8) * Mm + m0],     acc[j][2]);
        atomicAdd(&Sg[(size_t)(dw + gid + 8) * Mm + m0 + 1], acc[j][3]);
    }
    if (tid < Dd) atomicAdd(&g_w[head * Dd + tid], ksum[tid]);
}

// ---------------------------------------------------------------------------
// Kernel 2 (tensor): out[s,m] = (phi(q) @ S_t) / (phi(q).w + eps)
// grid (32, BH), 256 thr. Whole q-tile (128x128) and S_t in smem (1 pass).
// ---------------------------------------------------------------------------
#define PQ 132   // pitch % 32 == 4 -> conflict-free A loads
#define PS 136   // pitch % 32 == 8 -> conflict-free B loads
#define SM2_WORDS (128*PQ + 128*PS + 256)
#define SM2_BYTES (SM2_WORDS * 4)

__global__ void __launch_bounds__(256)
k_phase2(const float* __restrict__ qq, float* __restrict__ out) {
    extern __shared__ unsigned sm2[];
    unsigned (*qs)[PQ]  = (unsigned (*)[PQ])sm2;
    unsigned (*Ssm)[PS] = (unsigned (*)[PS])(sm2 + 128 * PQ);
    float* ws   = (float*)(sm2 + 128 * PQ + 128 * PS);
    float* dens = ws + 128;

    int head = blockIdx.y;
    int sbase = blockIdx.x * 128;
    int tid = threadIdx.x;
    int warp = tid >> 5, lane = tid & 31;
    int gid = lane >> 2, tig = lane & 3;
    int sw = warp * 16;

    const float* qh = qq + (size_t)head * Ss * Dd;
    const float* Sg = g_S + (size_t)head * Dd * Mm;

    for (int i = tid; i < 128 * 128; i += 256) {
        int r = i >> 7, c = i & 127;
        qs[r][c]  = f2tf(phi(qh[(size_t)(sbase + r) * Dd + c]));
        Ssm[r][c] = f2tf(Sg[i]);
    }
    if (tid < 128) ws[tid] = g_w[head * Dd + tid];
    __syncthreads();

    // den[s] = sum_d phi(q)[s,d] * w[d]  (2 threads per row)
    {
        int rrow = tid >> 1, half = tid & 1;
        float dsum = 0.f;
#pragma unroll 8
        for (int d = half * 64; d < half * 64 + 64; d++)
            dsum += __uint_as_float(qs[rrow][d]) * ws[d];
        dsum += __shfl_xor_sync(0xffffffffu, dsum, 1);
        if (half == 0) dens[rrow] = dsum;
    }
    __syncthreads();

    float acc[16][4];
#pragma unroll
    for (int j = 0; j < 16; j++)
#pragma unroll
        for (int t = 0; t < 4; t++) acc[j][t] = 0.f;

#pragma unroll
    for (int k0 = 0; k0 < 128; k0 += 8) {
        unsigned a[4];
        a[0] = qs[sw + gid][k0 + tig];
        a[1] = qs[sw + gid + 8][k0 + tig];
        a[2] = qs[sw + gid][k0 + tig + 4];
        a[3] = qs[sw + gid + 8][k0 + tig + 4];
#pragma unroll
        for (int j = 0; j < 16; j++) {
            unsigned b[2] = { Ssm[k0 + tig][j * 8 + gid],
                              Ssm[k0 + tig + 4][j * 8 + gid] };
            mma8(acc[j], a, b);
        }
    }

    float* oh = out + ((size_t)head * Ss + sbase) * Mm;
    float inv0 = 1.f / (dens[sw + gid] + EPSV);
    float inv1 = 1.f / (dens[sw + gid + 8] + EPSV);
#pragma unroll
    for (int j = 0; j < 16; j++) {
        int m0 = j * 8 + tig * 2;
        float2 r0 = make_float2(acc[j][0] * inv0, acc[j][1] * inv0);
        float2 r1 = make_float2(acc[j][2] * inv1, acc[j][3] * inv1);
        *(float2*)(oh + (size_t)(sw + gid) * Mm + m0) = r0;
        *(float2*)(oh + (size_t)(sw + gid + 8) * Mm + m0) = r1;
    }
}

// ---------------------------------------------------------------------------
// Kernel 3 (optional): copy S_t scratch into output region
// ---------------------------------------------------------------------------
__global__ void k_copyS(float* __restrict__ dst) {
    size_t i = (size_t)blockIdx.x * blockDim.x + threadIdx.x;
    if (i < (size_t)BH * Dd * Mm) dst[i] = g_S[i];
}

// ---------------------------------------------------------------------------
// Kernel 4 (optional): z_t[head,d,s] = z_prev[head,d] + phi(k)[head,s,d]*mask
// ---------------------------------------------------------------------------
__global__ void k_zt(const float* __restrict__ kk, const float* __restrict__ mask,
                     const float* __restrict__ z_prev, float* __restrict__ zt) {
    __shared__ float tile[32][33];
    int head = blockIdx.z;
    int s0 = blockIdx.x * 32;
    int d0 = blockIdx.y * 32;
    int tx = threadIdx.x, ty = threadIdx.y;   // 32 x 8
    const float* kh = kk + (size_t)head * Ss * Dd;
    const float* mh = mask + (size_t)head * Ss;
    for (int r = ty; r < 32; r += 8) {
        int s = s0 + r;
        tile[r][tx] = phi(kh[(size_t)s * Dd + d0 + tx]) * mh[s];
    }
    __syncthreads();
    float* zth = zt + (size_t)head * Dd * Ss;
    for (int r = ty; r < 32; r += 8) {
        int d = d0 + r;
        zth[(size_t)d * Ss + s0 + tx] = tile[tx][r] + z_prev[head * Dd + d];
    }
}

// ---------------------------------------------------------------------------
extern "C" void kernel_launch(void* const* d_in, const int* in_sizes, int n_in,
                              void* d_out, int out_size) {
    (void)in_sizes; (void)n_in;
    const float* q      = (const float*)d_in[0];
    const float* k      = (const float*)d_in[1];
    const float* v      = (const float*)d_in[2];
    const float* mask   = (const float*)d_in[3];
    const float* S_prev = (const float*)d_in[4];
    const float* z_prev = (const float*)d_in[5];
    float* out = (float*)d_out;

    cudaFuncSetAttribute(k_phase2, cudaFuncAttributeMaxDynamicSharedMemorySize,
                         SM2_BYTES);

    k_init<<<BH, 256>>>(S_prev, z_prev);

    dim3 g1(Ss / P1_CHUNK, BH);
    k_phase1<<<g1, 256>>>(k, v, mask);

    dim3 g2(Ss / 128, BH);
    k_phase2<<<g2, 256, SM2_BYTES>>>(q, out);

    const long N_OUT = (long)BH * Ss * Mm;
    const long N_ST  = (long)BH * Dd * Mm;
    const long N_ZT  = (long)BH * Dd * Ss;
    long osz = (long)out_size;
    if (osz >= N_OUT + N_ST) {
        k_copyS<<<(int)((N_ST + 255) / 256), 256>>>(out + N_OUT);
    }
    if (osz >= N_OUT + N_ST + N_ZT) {
        dim3 gz(Ss / 32, Dd / 32, BH);
        k_zt<<<gz, dim3(32, 8)>>>(k, mask, z_prev, out + N_OUT + N_ST);
    }
}

// round 3
// speedup vs baseline: 1.6217x; 1.5460x over previous
#include <cuda_runtime.h>
#include <math.h>

#define Bq 4
#define Hh 16
#define Ss 4096
#define Dd 128
#define Mm 128
#define BH (Bq*Hh)
#define EPSV 1e-6f

// Scratch (no cudaMalloc allowed)
__device__ float g_S[BH*Dd*Mm];   // S_t accumulator [BH, D, M]
__device__ float g_w[BH*Dd];      // w[d] = S*z_prev[d] + sum_s phi(k)[s,d]

__device__ __forceinline__ float phi(float x) {
    return x > 0.f ? x + 1.f : expf(x);
}
__device__ __forceinline__ unsigned f2tf(float x) {
    unsigned r; asm("cvt.rna.tf32.f32 %0, %1;" : "=r"(r) : "f"(x)); return r;
}
__device__ __forceinline__ void mma8(float* c, const unsigned* a, const unsigned* b) {
    asm volatile(
        "mma.sync.aligned.m16n8k8.row.col.f32.tf32.tf32.f32 "
        "{%0,%1,%2,%3}, {%4,%5,%6,%7}, {%8,%9}, {%0,%1,%2,%3};"
        : "+f"(c[0]), "+f"(c[1]), "+f"(c[2]), "+f"(c[3])
        : "r"(a[0]), "r"(a[1]), "r"(a[2]), "r"(a[3]), "r"(b[0]), "r"(b[1]));
}

// ---------------------------------------------------------------------------
// Kernel 0: init scratch: g_S = S_prev, g_w = S * z_prev
// ---------------------------------------------------------------------------
__global__ void k_init(const float* __restrict__ S_prev,
                       const float* __restrict__ z_prev) {
    int head = blockIdx.x;
    const float* sp = S_prev + (size_t)head * Dd * Mm;
    float* sg = g_S + (size_t)head * Dd * Mm;
    for (int i = threadIdx.x; i < Dd * Mm; i += blockDim.x)
        sg[i] = sp[i];
    for (int i = threadIdx.x; i < Dd; i += blockDim.x)
        g_w[head * Dd + i] = (float)Ss * z_prev[head * Dd + i];
}

// ---------------------------------------------------------------------------
// Kernel 1 (tensor): S_t += phi(k)^T * v  and  w += sum_s phi(k)
// grid (4, BH), 256 thr (8 warps). warp w owns d-rows [16w,16w+16), all 128 m.
// NOTE: thread's loaded column c = tid&127 is invariant -> private ksum, ONE
// global atomic per thread at the end (no per-element atomics).
// ---------------------------------------------------------------------------
#define P1_CHUNK 1024
#define P1_ST 32
#define PITCH1 136   // pitch % 32 == 8 -> conflict-free fragment LDS

__global__ void __launch_bounds__(256)
k_phase1(const float* __restrict__ kk, const float* __restrict__ vv,
         const float* __restrict__ mask) {
    int head = blockIdx.y;
    int sbase = blockIdx.x * P1_CHUNK;

    __shared__ unsigned ks[P1_ST][PITCH1];
    __shared__ unsigned vs[P1_ST][PITCH1];

    int tid = threadIdx.x;
    int warp = tid >> 5, lane = tid & 31;
    int gid = lane >> 2, tig = lane & 3;
    int dw = warp * 16;

    float ksumP = 0.f;   // private accumulator for column (tid & 127)

    float acc[16][4];
#pragma unroll
    for (int j = 0; j < 16; j++)
#pragma unroll
        for (int t = 0; t < 4; t++) acc[j][t] = 0.f;

    const float* kh = kk + (size_t)head * Ss * Dd;
    const float* vh = vv + (size_t)head * Ss * Mm;
    const float* mh = mask + (size_t)head * Ss;

    for (int s0 = sbase; s0 < sbase + P1_CHUNK; s0 += P1_ST) {
        __syncthreads();
#pragma unroll
        for (int t = 0; t < (P1_ST * Dd) / 256; t++) {
            int i = tid + t * 256;
            int r = i >> 7, c = i & 127;
            float mval = mh[s0 + r];
            float kv = phi(kh[(size_t)(s0 + r) * Dd + c]) * mval;
            ks[r][c] = f2tf(kv);
            ksumP += kv;
            vs[r][c] = f2tf(vh[(size_t)(s0 + r) * Mm + c] * mval);
        }
        __syncthreads();
#pragma unroll
        for (int k8 = 0; k8 < P1_ST; k8 += 8) {
            unsigned a[4];
            a[0] = ks[k8 + tig][dw + gid];
            a[1] = ks[k8 + tig][dw + gid + 8];
            a[2] = ks[k8 + tig + 4][dw + gid];
            a[3] = ks[k8 + tig + 4][dw + gid + 8];
#pragma unroll
            for (int j = 0; j < 16; j++) {
                unsigned b[2] = { vs[k8 + tig][j * 8 + gid],
                                  vs[k8 + tig + 4][j * 8 + gid] };
                mma8(acc[j], a, b);
            }
        }
    }

    float* Sg = g_S + (size_t)head * Dd * Mm;
#pragma unroll
    for (int j = 0; j < 16; j++) {
        int m0 = j * 8 + tig * 2;
        atomicAdd(&Sg[(size_t)(dw + gid) * Mm + m0],     acc[j][0]);
        atomicAdd(&Sg[(size_t)(dw + gid) * Mm + m0 + 1], acc[j][1]);
        atomicAdd(&Sg[(size_t)(dw + gid + 8) * Mm + m0],     acc[j][2]);
        atomicAdd(&Sg[(size_t)(dw + gid + 8) * Mm + m0 + 1], acc[j][3]);
    }
    atomicAdd(&g_w[head * Dd + (tid & 127)], ksumP);
}

// ---------------------------------------------------------------------------
// Kernel 2 (tensor): out[s,m] = (phi(q) @ S_t) / (phi(q).w + eps)
// grid (32, BH), 256 thr. Whole q-tile (128x128) and S_t in smem (1 pass).
// ---------------------------------------------------------------------------
#define PQ 132   // pitch % 32 == 4 -> conflict-free A loads
#define PS 136   // pitch % 32 == 8 -> conflict-free B loads
#define SM2_WORDS (128*PQ + 128*PS + 256)
#define SM2_BYTES (SM2_WORDS * 4)

__global__ void __launch_bounds__(256)
k_phase2(const float* __restrict__ qq, float* __restrict__ out) {
    extern __shared__ unsigned sm2[];
    unsigned (*qs)[PQ]  = (unsigned (*)[PQ])sm2;
    unsigned (*Ssm)[PS] = (unsigned (*)[PS])(sm2 + 128 * PQ);
    float* ws   = (float*)(sm2 + 128 * PQ + 128 * PS);
    float* dens = ws + 128;

    int head = blockIdx.y;
    int sbase = blockIdx.x * 128;
    int tid = threadIdx.x;
    int warp = tid >> 5, lane = tid & 31;
    int gid = lane >> 2, tig = lane & 3;
    int sw = warp * 16;

    const float* qh = qq + (size_t)head * Ss * Dd;
    const float* Sg = g_S + (size_t)head * Dd * Mm;

    for (int i = tid; i < 128 * 128; i += 256) {
        int r = i >> 7, c = i & 127;
        qs[r][c]  = f2tf(phi(qh[(size_t)(sbase + r) * Dd + c]));
        Ssm[r][c] = f2tf(Sg[i]);
    }
    if (tid < 128) ws[tid] = g_w[head * Dd + tid];
    __syncthreads();

    // den[s] = sum_d phi(q)[s,d] * w[d]  (2 threads per row)
    {
        int rrow = tid >> 1, half = tid & 1;
        float dsum = 0.f;
#pragma unroll 8
        for (int d = half * 64; d < half * 64 + 64; d++)
            dsum += __uint_as_float(qs[rrow][d]) * ws[d];
        dsum += __shfl_xor_sync(0xffffffffu, dsum, 1);
        if (half == 0) dens[rrow] = dsum;
    }
    __syncthreads();

    float acc[16][4];
#pragma unroll
    for (int j = 0; j < 16; j++)
#pragma unroll
        for (int t = 0; t < 4; t++) acc[j][t] = 0.f;

#pragma unroll
    for (int k0 = 0; k0 < 128; k0 += 8) {
        unsigned a[4];
        a[0] = qs[sw + gid][k0 + tig];
        a[1] = qs[sw + gid + 8][k0 + tig];
        a[2] = qs[sw + gid][k0 + tig + 4];
        a[3] = qs[sw + gid + 8][k0 + tig + 4];
#pragma unroll
        for (int j = 0; j < 16; j++) {
            unsigned b[2] = { Ssm[k0 + tig][j * 8 + gid],
                              Ssm[k0 + tig + 4][j * 8 + gid] };
            mma8(acc[j], a, b);
        }
    }

    float* oh = out + ((size_t)head * Ss + sbase) * Mm;
    float inv0 = 1.f / (dens[sw + gid] + EPSV);
    float inv1 = 1.f / (dens[sw + gid + 8] + EPSV);
#pragma unroll
    for (int j = 0; j < 16; j++) {
        int m0 = j * 8 + tig * 2;
        float2 r0 = make_float2(acc[j][0] * inv0, acc[j][1] * inv0);
        float2 r1 = make_float2(acc[j][2] * inv1, acc[j][3] * inv1);
        *(float2*)(oh + (size_t)(sw + gid) * Mm + m0) = r0;
        *(float2*)(oh + (size_t)(sw + gid + 8) * Mm + m0) = r1;
    }
}

// ---------------------------------------------------------------------------
// Kernel 3 (optional): copy S_t scratch into output region
// ---------------------------------------------------------------------------
__global__ void k_copyS(float* __restrict__ dst) {
    size_t i = (size_t)blockIdx.x * blockDim.x + threadIdx.x;
    if (i < (size_t)BH * Dd * Mm) dst[i] = g_S[i];
}

// ---------------------------------------------------------------------------
// Kernel 4 (optional): z_t[head,d,s] = z_prev[head,d] + phi(k)[head,s,d]*mask
// ---------------------------------------------------------------------------
__global__ void k_zt(const float* __restrict__ kk, const float* __restrict__ mask,
                     const float* __restrict__ z_prev, float* __restrict__ zt) {
    __shared__ float tile[32][33];
    int head = blockIdx.z;
    int s0 = blockIdx.x * 32;
    int d0 = blockIdx.y * 32;
    int tx = threadIdx.x, ty = threadIdx.y;   // 32 x 8
    const float* kh = kk + (size_t)head * Ss * Dd;
    const float* mh = mask + (size_t)head * Ss;
    for (int r = ty; r < 32; r += 8) {
        int s = s0 + r;
        tile[r][tx] = phi(kh[(size_t)s * Dd + d0 + tx]) * mh[s];
    }
    __syncthreads();
    float* zth = zt + (size_t)head * Dd * Ss;
    for (int r = ty; r < 32; r += 8) {
        int d = d0 + r;
        zth[(size_t)d * Ss + s0 + tx] = tile[tx][r] + z_prev[head * Dd + d];
    }
}

// ---------------------------------------------------------------------------
extern "C" void kernel_launch(void* const* d_in, const int* in_sizes, int n_in,
                              void* d_out, int out_size) {
    (void)in_sizes; (void)n_in;
    const float* q      = (const float*)d_in[0];
    const float* k      = (const float*)d_in[1];
    const float* v      = (const float*)d_in[2];
    const float* mask   = (const float*)d_in[3];
    const float* S_prev = (const float*)d_in[4];
    const float* z_prev = (const float*)d_in[5];
    float* out = (float*)d_out;

    cudaFuncSetAttribute(k_phase2, cudaFuncAttributeMaxDynamicSharedMemorySize,
                         SM2_BYTES);

    k_init<<<BH, 256>>>(S_prev, z_prev);

    dim3 g1(Ss / P1_CHUNK, BH);
    k_phase1<<<g1, 256>>>(k, v, mask);

    dim3 g2(Ss / 128, BH);
    k_phase2<<<g2, 256, SM2_BYTES>>>(q, out);

    const long N_OUT = (long)BH * Ss * Mm;
    const long N_ST  = (long)BH * Dd * Mm;
    const long N_ZT  = (long)BH * Dd * Ss;
    long osz = (long)out_size;
    if (osz >= N_OUT + N_ST) {
        k_copyS<<<(int)((N_ST + 255) / 256), 256>>>(out + N_OUT);
    }
    if (osz >= N_OUT + N_ST + N_ZT) {
        dim3 gz(Ss / 32, Dd / 32, BH);
        k_zt<<<gz, dim3(32, 8)>>>(k, mask, z_prev, out + N_OUT + N_ST);
    }
}

// round 5
// speedup vs baseline: 1.8221x; 1.1236x over previous
#include <cuda_runtime.h>
#include <cstdint>
#include <math.h>

#define Bq 4
#define Hh 16
#define Ss 4096
#define Dd 128
#define Mm 128
#define BH (Bq*Hh)
#define EPSV 1e-6f

// Scratch (no cudaMalloc allowed)
__device__ float g_S [BH*Dd*Mm];  // S_t accumulator [BH, D, M]
__device__ float g_ST[BH*Dd*Mm];  // S_t transposed  [BH, M, D] (tf32 bits)
__device__ float g_w [BH*Dd];     // w[d] = S*z_prev[d] + sum_s phi(k)[s,d]

__device__ __forceinline__ float phi(float x) {
    return x > 0.f ? x + 1.f : expf(x);
}
__device__ __forceinline__ unsigned f2tf(float x) {
    unsigned r; asm("cvt.rna.tf32.f32 %0, %1;" : "=r"(r) : "f"(x)); return r;
}
__device__ __forceinline__ unsigned s2u(const void* p) {
    unsigned a;
    asm("{ .reg .u64 t; cvta.to.shared.u64 t, %1; cvt.u32.u64 %0, t; }"
        : "=r"(a) : "l"(p));
    return a;
}
__device__ __forceinline__ void mma8(float* c, const unsigned* a, const unsigned* b) {
    asm volatile(
        "mma.sync.aligned.m16n8k8.row.col.f32.tf32.tf32.f32 "
        "{%0,%1,%2,%3}, {%4,%5,%6,%7}, {%8,%9}, {%0,%1,%2,%3};"
        : "+f"(c[0]), "+f"(c[1]), "+f"(c[2]), "+f"(c[3])
        : "r"(a[0]), "r"(a[1]), "r"(a[2]), "r"(a[3]), "r"(b[0]), "r"(b[1]));
}
__device__ __forceinline__ void ldsm4(unsigned* r, unsigned a) {
    asm volatile("ldmatrix.sync.aligned.m8n8.x4.shared.b16 {%0,%1,%2,%3}, [%4];"
        : "=r"(r[0]), "=r"(r[1]), "=r"(r[2]), "=r"(r[3]) : "r"(a));
}

// ---------------------------------------------------------------------------
// Kernel 0: init scratch
// ---------------------------------------------------------------------------
__global__ void k_init(const float* __restrict__ S_prev,
                       const float* __restrict__ z_prev) {
    int head = blockIdx.x;
    const float* sp = S_prev + (size_t)head * Dd * Mm;
    float* sg = g_S + (size_t)head * Dd * Mm;
    for (int i = threadIdx.x; i < Dd * Mm; i += blockDim.x)
        sg[i] = sp[i];
    for (int i = threadIdx.x; i < Dd; i += blockDim.x)
        g_w[head * Dd + i] = (float)Ss * z_prev[head * Dd + i];
}

// ---------------------------------------------------------------------------
// Kernel 1 (tensor + LDSM): S_t += phi(k)^T v ; w += sum_s phi(k)
// grid (4, BH), 256 thr (8 warps). Warp tile 32d x 64m.
// ksT[d][s16], vsT[m][s16] pitch 20 words (80B rows: conflict-free STS.128/LDSM).
// ---------------------------------------------------------------------------
#define P1_CHUNK 1024
#define P1S 16
#define P1P 20

__global__ void __launch_bounds__(256)
k_phase1(const float* __restrict__ kk, const float* __restrict__ vv,
         const float* __restrict__ mask) {
    int head = blockIdx.y;
    int sbase = blockIdx.x * P1_CHUNK;

    __shared__ unsigned ksT[Dd][P1P];   // [d][s]
    __shared__ unsigned vsT[Mm][P1P];   // [m][s]

    int tid = threadIdx.x;
    int warp = tid >> 5, lane = tid & 31;
    int gid = lane >> 2, tig = lane & 3;
    int d0 = (warp >> 1) * 32;
    int m0 = (warp & 1) * 64;
    int c  = tid & 127;          // column this thread stages (d for k, m for v)
    int sg = (tid >> 7) * 8;     // row base within stage (0 or 8)

    // per-lane LDSM base addresses
    int sel = lane >> 3, lrow = lane & 7;
    unsigned aBase = s2u(ksT) +
        (((d0 + (sel & 1) * 8 + lrow) * P1P + (sel >> 1) * 4) << 2);
    unsigned bBase = s2u(vsT) +
        (((m0 + (sel >> 1) * 8 + lrow) * P1P + (sel & 1) * 4) << 2);

    float ksumP = 0.f;
    float acc[2][8][4];
#pragma unroll
    for (int ah = 0; ah < 2; ah++)
#pragma unroll
        for (int bi = 0; bi < 8; bi++)
#pragma unroll
            for (int t = 0; t < 4; t++) acc[ah][bi][t] = 0.f;

    const float* kh = kk + (size_t)head * Ss * Dd;
    const float* vh = vv + (size_t)head * Ss * Mm;
    const float* mh = mask + (size_t)head * Ss;

    float kr[8], vr[8];
    // prologue: load stage 0 into regs
#pragma unroll
    for (int e = 0; e < 8; e++) {
        int s = sbase + sg + e;
        float mv = mh[s];
        kr[e] = phi(kh[(size_t)s * Dd + c]) * mv;
        vr[e] = vh[(size_t)s * Mm + c] * mv;
    }

    const int NSTAGE = P1_CHUNK / P1S;   // 64
    for (int t = 0; t < NSTAGE; t++) {
        __syncthreads();   // previous stage fully consumed
        // store staged regs (transposed) + ksum
#pragma unroll
        for (int g = 0; g < 2; g++) {
            uint4 kp, vp;
            kp.x = f2tf(kr[g*4+0]); kp.y = f2tf(kr[g*4+1]);
            kp.z = f2tf(kr[g*4+2]); kp.w = f2tf(kr[g*4+3]);
            vp.x = f2tf(vr[g*4+0]); vp.y = f2tf(vr[g*4+1]);
            vp.z = f2tf(vr[g*4+2]); vp.w = f2tf(vr[g*4+3]);
            *(uint4*)&ksT[c][sg + g*4] = kp;
            *(uint4*)&vsT[c][sg + g*4] = vp;
        }
#pragma unroll
        for (int e = 0; e < 8; e++) ksumP += kr[e];
        __syncthreads();   // tile ready

        // prefetch next stage (LDG latency overlaps MMA below)
        if (t + 1 < NSTAGE) {
            int s0n = sbase + (t + 1) * P1S;
#pragma unroll
            for (int e = 0; e < 8; e++) {
                int s = s0n + sg + e;
                float mv = mh[s];
                kr[e] = phi(kh[(size_t)s * Dd + c]) * mv;
                vr[e] = vh[(size_t)s * Mm + c] * mv;
            }
        }

        // MMA over this stage's 16 s-values
#pragma unroll
        for (int k8 = 0; k8 < P1S; k8 += 8) {
            unsigned A[2][4], B[4][4];
            ldsm4(A[0], aBase + (k8 << 2));
            ldsm4(A[1], aBase + ((16 * P1P + k8) << 2));
#pragma unroll
            for (int q = 0; q < 4; q++)
                ldsm4(B[q], bBase + ((q * 16 * P1P + k8) << 2));
#pragma unroll
            for (int ah = 0; ah < 2; ah++)
#pragma unroll
                for (int bi = 0; bi < 8; bi++)
                    mma8(acc[ah][bi], A[ah], &B[bi >> 1][(bi & 1) * 2]);
        }
    }

    float* Sg = g_S + (size_t)head * Dd * Mm;
#pragma unroll
    for (int ah = 0; ah < 2; ah++)
#pragma unroll
        for (int bi = 0; bi < 8; bi++) {
            int dr = d0 + ah * 16 + gid;
            int mc = m0 + bi * 8 + tig * 2;
            atomicAdd(&Sg[(size_t)dr * Mm + mc],       acc[ah][bi][0]);
            atomicAdd(&Sg[(size_t)dr * Mm + mc + 1],   acc[ah][bi][1]);
            atomicAdd(&Sg[(size_t)(dr+8) * Mm + mc],   acc[ah][bi][2]);
            atomicAdd(&Sg[(size_t)(dr+8) * Mm + mc+1], acc[ah][bi][3]);
        }
    atomicAdd(&g_w[head * Dd + c], ksumP);
}

// ---------------------------------------------------------------------------
// Kernel 1b: transpose S_t -> g_ST [m][d] with tf32 conversion baked in
// ---------------------------------------------------------------------------
__global__ void k_transS(void) {
    __shared__ float tile[32][33];
    int head = blockIdx.z;
    int db = blockIdx.x * 32, mb = blockIdx.y * 32;
    int tx = threadIdx.x, ty = threadIdx.y;   // 32 x 8
    const float* Sg = g_S + (size_t)head * Dd * Mm;
    float* STg = g_ST + (size_t)head * Dd * Mm;
    for (int r = ty; r < 32; r += 8)
        tile[r][tx] = Sg[(size_t)(db + r) * Mm + mb + tx];
    __syncthreads();
    for (int r = ty; r < 32; r += 8)
        STg[(size_t)(mb + r) * Dd + db + tx] =
            __uint_as_float(f2tf(tile[tx][r]));
}

// ---------------------------------------------------------------------------
// Kernel 2 (tensor + LDSM): out = (phi(q) @ S_t) / (phi(q).w + eps)
// grid (32, BH), 256 thr. Warp tile 32s x 64m. qs/STs pitch 132 (528B rows).
// ---------------------------------------------------------------------------
#define PQ 132
#define SM2_WORDS (128*PQ + 128*PQ + 256)
#define SM2_BYTES (SM2_WORDS * 4)

__global__ void __launch_bounds__(256)
k_phase2(const float* __restrict__ qq, float* __restrict__ out) {
    extern __shared__ unsigned sm2[];
    unsigned (*qs)[PQ]  = (unsigned (*)[PQ])sm2;            // [s][d] tf32
    unsigned (*STs)[PQ] = (unsigned (*)[PQ])(sm2 + 128*PQ); // [m][d] tf32
    float* ws   = (float*)(sm2 + 2 * 128 * PQ);
    float* dens = ws + 128;

    int head = blockIdx.y;
    int sbase = blockIdx.x * 128;
    int tid = threadIdx.x;
    int warp = tid >> 5, lane = tid & 31;
    int gid = lane >> 2, tig = lane & 3;
    int sw = (warp >> 1) * 32;
    int m0 = (warp & 1) * 64;

    const float* qh = qq + (size_t)head * Ss * Dd;
    const float* STg = g_ST + (size_t)head * Dd * Mm;

    for (int i = tid; i < 128 * 128; i += 256) {
        int r = i >> 7, cc = i & 127;
        qs[r][cc]  = f2tf(phi(qh[(size_t)(sbase + r) * Dd + cc]));
        STs[r][cc] = __float_as_uint(STg[i]);
    }
    if (tid < 128) ws[tid] = g_w[head * Dd + tid];
    __syncthreads();

    // den[s] = sum_d phi(q)[s,d] * w[d]
    {
        int rrow = tid >> 1, half = tid & 1;
        float dsum = 0.f;
#pragma unroll 8
        for (int d = half * 64; d < half * 64 + 64; d++)
            dsum += __uint_as_float(qs[rrow][d]) * ws[d];
        dsum += __shfl_xor_sync(0xffffffffu, dsum, 1);
        if (half == 0) dens[rrow] = dsum;
    }
    __syncthreads();

    int sel = lane >> 3, lrow = lane & 7;
    unsigned aBase = s2u(qs) +
        (((sw + (sel & 1) * 8 + lrow) * PQ + (sel >> 1) * 4) << 2);
    unsigned bBase = s2u(STs) +
        (((m0 + (sel >> 1) * 8 + lrow) * PQ + (sel & 1) * 4) << 2);

    float acc[2][8][4];
#pragma unroll
    for (int ah = 0; ah < 2; ah++)
#pragma unroll
        for (int bi = 0; bi < 8; bi++)
#pragma unroll
            for (int t = 0; t < 4; t++) acc[ah][bi][t] = 0.f;

#pragma unroll
    for (int k0 = 0; k0 < 128; k0 += 8) {
        unsigned A[2][4], B[4][4];
        ldsm4(A[0], aBase + (k0 << 2));
        ldsm4(A[1], aBase + ((16 * PQ + k0) << 2));
#pragma unroll
        for (int q = 0; q < 4; q++)
            ldsm4(B[q], bBase + ((q * 16 * PQ + k0) << 2));
#pragma unroll
        for (int ah = 0; ah < 2; ah++)
#pragma unroll
            for (int bi = 0; bi < 8; bi++)
                mma8(acc[ah][bi], A[ah], &B[bi >> 1][(bi & 1) * 2]);
    }

    float* oh = out + ((size_t)head * Ss + sbase) * Mm;
#pragma unroll
    for (int ah = 0; ah < 2; ah++) {
        int sr = sw + ah * 16 + gid;
        float inv0 = 1.f / (dens[sr] + EPSV);
        float inv1 = 1.f / (dens[sr + 8] + EPSV);
#pragma unroll
        for (int bi = 0; bi < 8; bi++) {
            int mc = m0 + bi * 8 + tig * 2;
            float2 r0 = make_float2(acc[ah][bi][0] * inv0, acc[ah][bi][1] * inv0);
            float2 r1 = make_float2(acc[ah][bi][2] * inv1, acc[ah][bi][3] * inv1);
            *(float2*)(oh + (size_t)sr * Mm + mc) = r0;
            *(float2*)(oh + (size_t)(sr + 8) * Mm + mc) = r1;
        }
    }
}

// ---------------------------------------------------------------------------
// Kernel 3 (optional): copy S_t scratch into output region
// ---------------------------------------------------------------------------
__global__ void k_copyS(float* __restrict__ dst) {
    size_t i = (size_t)blockIdx.x * blockDim.x + threadIdx.x;
    if (i < (size_t)BH * Dd * Mm) dst[i] = g_S[i];
}

// ---------------------------------------------------------------------------
// Kernel 4 (optional): z_t[head,d,s] = z_prev[head,d] + phi(k)[head,s,d]*mask
// ---------------------------------------------------------------------------
__global__ void k_zt(const float* __restrict__ kk, const float* __restrict__ mask,
                     const float* __restrict__ z_prev, float* __restrict__ zt) {
    __shared__ float tile[32][33];
    int head = blockIdx.z;
    int s0 = blockIdx.x * 32;
    int d0 = blockIdx.y * 32;
    int tx = threadIdx.x, ty = threadIdx.y;   // 32 x 8
    const float* kh = kk + (size_t)head * Ss * Dd;
    const float* mh = mask + (size_t)head * Ss;
    for (int r = ty; r < 32; r += 8) {
        int s = s0 + r;
        tile[r][tx] = phi(kh[(size_t)s * Dd + d0 + tx]) * mh[s];
    }
    __syncthreads();
    float* zth = zt + (size_t)head * Dd * Ss;
    for (int r = ty; r < 32; r += 8) {
        int d = d0 + r;
        zth[(size_t)d * Ss + s0 + tx] = tile[tx][r] + z_prev[head * Dd + d];
    }
}

// ---------------------------------------------------------------------------
extern "C" void kernel_launch(void* const* d_in, const int* in_sizes, int n_in,
                              void* d_out, int out_size) {
    (void)in_sizes; (void)n_in;
    const float* q      = (const float*)d_in[0];
    const float* k      = (const float*)d_in[1];
    const float* v      = (const float*)d_in[2];
    const float* mask   = (const float*)d_in[3];
    const float* S_prev = (const float*)d_in[4];
    const float* z_prev = (const float*)d_in[5];
    float* out = (float*)d_out;

    cudaFuncSetAttribute(k_phase2, cudaFuncAttributeMaxDynamicSharedMemorySize,
                         SM2_BYTES);

    k_init<<<BH, 256>>>(S_prev, z_prev);

    dim3 g1(Ss / P1_CHUNK, BH);
    k_phase1<<<g1, 256>>>(k, v, mask);

    dim3 gt(Dd / 32, Mm / 32, BH);
    k_transS<<<gt, dim3(32, 8)>>>();

    dim3 g2(Ss / 128, BH);
    k_phase2<<<g2, 256, SM2_BYTES>>>(q, out);

    const long N_OUT = (long)BH * Ss * Mm;
    const long N_ST  = (long)BH * Dd * Mm;
    const long N_ZT  = (long)BH * Dd * Ss;
    long osz = (long)out_size;
    if (osz >= N_OUT + N_ST) {
        k_copyS<<<(int)((N_ST + 255) / 256), 256>>>(out + N_OUT);
    }
    if (osz >= N_OUT + N_ST + N_ZT) {
        dim3 gz(Ss / 32, Dd / 32, BH);
        k_zt<<<gz, dim3(32, 8)>>>(k, mask, z_prev, out + N_OUT + N_ST);
    }
}